// round 1
// baseline (speedup 1.0000x reference)
#include <cuda_runtime.h>

#define NBATCH  4
#define NPTS    8192
#define THREADS 512
#define CHUNKS  (NPTS / THREADS)   // 16

// Partial sums: [dir][batch][chunk]. Every slot is overwritten each launch.
__device__ float g_partial[2 * NBATCH * CHUNKS];

typedef unsigned long long ull;

__device__ __forceinline__ ull ffma2(ull a, ull b, ull c) {
    ull d;
    asm("fma.rn.f32x2 %0, %1, %2, %3;" : "=l"(d) : "l"(a), "l"(b), "l"(c));
    return d;
}
__device__ __forceinline__ ull pack2(float lo, float hi) {
    ull d;
    asm("mov.b64 %0, {%1, %2};" : "=l"(d) : "f"(lo), "f"(hi));
    return d;
}
__device__ __forceinline__ float2 unpack2(ull v) {
    float2 r;
    asm("mov.b64 {%0, %1}, %2;" : "=f"(r.x), "=f"(r.y) : "l"(v));
    return r;
}

__global__ __launch_bounds__(THREADS, 1)
void chamfer_main(const float* __restrict__ rec, const float* __restrict__ data) {
    extern __shared__ float smem[];
    float* s0 = smem;               // y0 of all 8192 db points
    float* s1 = smem + NPTS;        // y1
    float* s2 = smem + 2 * NPTS;    // y2
    float* sn = smem + 3 * NPTS;    // ||y||^2

    const int tid   = threadIdx.x;
    const int chunk = blockIdx.x;
    const int b     = blockIdx.y;
    const int dir   = blockIdx.z;

    // dir 0: queries = rec, database = data  (rec_dist)
    // dir 1: queries = data, database = rec  (data_dist)
    const float* __restrict__ qry = dir ? data : rec;
    const float* __restrict__ db  = dir ? rec  : data;

    // ---- Load full database batch into SMEM (SoA + precomputed norms) ----
    const float* dbb = db + (size_t)b * NPTS * 3;
    #pragma unroll
    for (int k = 0; k < NPTS / THREADS; ++k) {
        int i = tid + k * THREADS;
        float x = dbb[3 * i + 0];
        float y = dbb[3 * i + 1];
        float z = dbb[3 * i + 2];
        s0[i] = x;
        s1[i] = y;
        s2[i] = z;
        sn[i] = fmaf(x, x, fmaf(y, y, z * z));
    }

    // ---- Per-thread query point ----
    const int qi = chunk * THREADS + tid;
    const float* qp = qry + ((size_t)b * NPTS + qi) * 3;
    float qx = qp[0], qy = qp[1], qz = qp[2];
    float q2 = fmaf(qx, qx, fmaf(qy, qy, qz * qz));
    ull A0 = pack2(-2.0f * qx, -2.0f * qx);
    ull A1 = pack2(-2.0f * qy, -2.0f * qy);
    ull A2 = pack2(-2.0f * qz, -2.0f * qz);

    __syncthreads();

    // ---- Main loop: min_j ( ||y_j||^2 - 2 x . y_j ), 4 points per step ----
    float m0 = 1e30f, m1 = 1e30f, m2 = 1e30f, m3 = 1e30f;

    #pragma unroll 8
    for (int j = 0; j < NPTS; j += 4) {
        ulonglong2 p0 = *reinterpret_cast<const ulonglong2*>(s0 + j);
        ulonglong2 p1 = *reinterpret_cast<const ulonglong2*>(s1 + j);
        ulonglong2 p2 = *reinterpret_cast<const ulonglong2*>(s2 + j);
        ulonglong2 pn = *reinterpret_cast<const ulonglong2*>(sn + j);

        ull accA = ffma2(A2, p2.x, pn.x);
        accA = ffma2(A1, p1.x, accA);
        accA = ffma2(A0, p0.x, accA);

        ull accB = ffma2(A2, p2.y, pn.y);
        accB = ffma2(A1, p1.y, accB);
        accB = ffma2(A0, p0.y, accB);

        float2 fa = unpack2(accA);
        float2 fb = unpack2(accB);
        m0 = fminf(m0, fa.x);
        m1 = fminf(m1, fa.y);
        m2 = fminf(m2, fb.x);
        m3 = fminf(m3, fb.y);
    }

    float mmin = fminf(fminf(m0, m1), fminf(m2, m3));
    float dist = fmaxf(q2 + mmin, 0.0f);   // clamp like reference's maximum(d,0)

    // ---- Deterministic block tree-sum ----
    __syncthreads();                 // everyone done reading db tiles
    smem[tid] = dist;
    __syncthreads();
    #pragma unroll
    for (int s = THREADS / 2; s > 0; s >>= 1) {
        if (tid < s) smem[tid] += smem[tid + s];
        __syncthreads();
    }
    if (tid == 0) {
        g_partial[(dir * NBATCH + b) * CHUNKS + chunk] = smem[0];
    }
}

__global__ void chamfer_finalize(float* __restrict__ out) {
    if (threadIdx.x == 0) {
        float total = 0.0f;
        #pragma unroll
        for (int b = 0; b < NBATCH; ++b) {
            float s_rec = 0.0f, s_dat = 0.0f;
            #pragma unroll
            for (int c = 0; c < CHUNKS; ++c) {
                s_rec += g_partial[(0 * NBATCH + b) * CHUNKS + c];
                s_dat += g_partial[(1 * NBATCH + b) * CHUNKS + c];
            }
            float mean_rec = s_rec * (1.0f / NPTS);
            float mean_dat = s_dat * (1.0f / NPTS);
            total += fmaxf(mean_rec, mean_dat);
        }
        out[0] = total * (1.0f / NBATCH);
    }
}

extern "C" void kernel_launch(void* const* d_in, const int* in_sizes, int n_in,
                              void* d_out, int out_size) {
    const float* rec  = (const float*)d_in[0];   // (B, N, 3) fp32
    const float* data = (const float*)d_in[1];   // (B, M, 3) fp32
    float* out = (float*)d_out;

    const size_t smem_bytes = 4 * NPTS * sizeof(float);  // 128 KB
    cudaFuncSetAttribute(chamfer_main,
                         cudaFuncAttributeMaxDynamicSharedMemorySize,
                         (int)smem_bytes);

    dim3 grid(CHUNKS, NBATCH, 2);
    chamfer_main<<<grid, THREADS, smem_bytes>>>(rec, data);
    chamfer_finalize<<<1, 32>>>(out);
}

// round 2
// speedup vs baseline: 1.3341x; 1.3341x over previous
#include <cuda_runtime.h>

#define NBATCH  4
#define NPTS    8192
#define THREADS 256
#define QPT     2                      // queries per thread
#define QBLK    (THREADS * QPT)        // 512 queries per block
#define CHUNKS  (NPTS / QBLK)          // 16
#define TOTAL_BLOCKS (CHUNKS * NBATCH * 2)  // 128

// Partial sums: [dir][batch][chunk]. Every slot is overwritten each launch.
__device__ float        g_partial[2 * NBATCH * CHUNKS];
__device__ unsigned int g_arrive;      // zero-init; last block resets to 0 each run

typedef unsigned long long ull;

__device__ __forceinline__ ull ffma2(ull a, ull b, ull c) {
    ull d;
    asm("fma.rn.f32x2 %0, %1, %2, %3;" : "=l"(d) : "l"(a), "l"(b), "l"(c));
    return d;
}
__device__ __forceinline__ ull pack2(float lo, float hi) {
    ull d;
    asm("mov.b64 %0, {%1, %2};" : "=l"(d) : "f"(lo), "f"(hi));
    return d;
}
__device__ __forceinline__ float2 unpack2(ull v) {
    float2 r;
    asm("mov.b64 {%0, %1}, %2;" : "=f"(r.x), "=f"(r.y) : "l"(v));
    return r;
}

__global__ __launch_bounds__(THREADS, 1)
void chamfer_main(const float* __restrict__ rec,
                  const float* __restrict__ data,
                  float* __restrict__ out) {
    extern __shared__ float smem[];
    float* s0 = smem;               // y0 of all 8192 db points
    float* s1 = smem + NPTS;        // y1
    float* s2 = smem + 2 * NPTS;    // y2
    float* sn = smem + 3 * NPTS;    // ||y||^2

    const int tid   = threadIdx.x;
    const int chunk = blockIdx.x;
    const int b     = blockIdx.y;
    const int dir   = blockIdx.z;

    // dir 0: queries = rec, database = data   (rec_dist)
    // dir 1: queries = data, database = rec   (data_dist)
    const float* __restrict__ qry = dir ? data : rec;
    const float* __restrict__ db  = dir ? rec  : data;

    // ---- Load full database batch into SMEM (SoA + precomputed norms) ----
    const float* dbb = db + (size_t)b * NPTS * 3;
    #pragma unroll
    for (int k = 0; k < NPTS / THREADS; ++k) {
        int i = tid + k * THREADS;
        float x = dbb[3 * i + 0];
        float y = dbb[3 * i + 1];
        float z = dbb[3 * i + 2];
        s0[i] = x;
        s1[i] = y;
        s2[i] = z;
        sn[i] = fmaf(x, x, fmaf(y, y, z * z));
    }

    // ---- Per-thread query points (2, coalesced across warp) ----
    float q2[QPT];
    ull A0[QPT], A1[QPT], A2[QPT];
    #pragma unroll
    for (int q = 0; q < QPT; ++q) {
        int qi = chunk * QBLK + q * THREADS + tid;
        const float* qp = qry + ((size_t)b * NPTS + qi) * 3;
        float qx = qp[0], qy = qp[1], qz = qp[2];
        q2[q] = fmaf(qx, qx, fmaf(qy, qy, qz * qz));
        A0[q] = pack2(-2.0f * qx, -2.0f * qx);
        A1[q] = pack2(-2.0f * qy, -2.0f * qy);
        A2[q] = pack2(-2.0f * qz, -2.0f * qz);
    }

    __syncthreads();

    // ---- Main loop: min_j ( ||y_j||^2 - 2 x . y_j ), 4 db points / step,
    //      2 queries / thread -> each LDS.128 feeds 2x the FFMA2 work ----
    float m0[QPT], m1[QPT], m2[QPT], m3[QPT];
    #pragma unroll
    for (int q = 0; q < QPT; ++q) { m0[q] = m1[q] = m2[q] = m3[q] = 1e30f; }

    #pragma unroll 4
    for (int j = 0; j < NPTS; j += 4) {
        ulonglong2 p0 = *reinterpret_cast<const ulonglong2*>(s0 + j);
        ulonglong2 p1 = *reinterpret_cast<const ulonglong2*>(s1 + j);
        ulonglong2 p2 = *reinterpret_cast<const ulonglong2*>(s2 + j);
        ulonglong2 pn = *reinterpret_cast<const ulonglong2*>(sn + j);

        #pragma unroll
        for (int q = 0; q < QPT; ++q) {
            ull accA = ffma2(A2[q], p2.x, pn.x);
            accA     = ffma2(A1[q], p1.x, accA);
            accA     = ffma2(A0[q], p0.x, accA);

            ull accB = ffma2(A2[q], p2.y, pn.y);
            accB     = ffma2(A1[q], p1.y, accB);
            accB     = ffma2(A0[q], p0.y, accB);

            float2 fa = unpack2(accA);
            float2 fb = unpack2(accB);
            m0[q] = fminf(m0[q], fa.x);
            m1[q] = fminf(m1[q], fa.y);
            m2[q] = fminf(m2[q], fb.x);
            m3[q] = fminf(m3[q], fb.y);
        }
    }

    float mysum = 0.0f;
    #pragma unroll
    for (int q = 0; q < QPT; ++q) {
        float mmin = fminf(fminf(m0[q], m1[q]), fminf(m2[q], m3[q]));
        mysum += fmaxf(q2[q] + mmin, 0.0f);   // clamp like reference's maximum(d,0)
    }

    // ---- Deterministic block tree-sum (reuse smem after sync) ----
    __syncthreads();
    smem[tid] = mysum;
    __syncthreads();
    #pragma unroll
    for (int s = THREADS / 2; s > 0; s >>= 1) {
        if (tid < s) smem[tid] += smem[tid + s];
        __syncthreads();
    }

    // ---- Fused finalize: last block to arrive computes the scalar ----
    if (tid == 0) {
        g_partial[(dir * NBATCH + b) * CHUNKS + chunk] = smem[0];
        __threadfence();
        unsigned int ticket = atomicAdd(&g_arrive, 1u);
        if (ticket == TOTAL_BLOCKS - 1) {
            float total = 0.0f;
            #pragma unroll
            for (int bb = 0; bb < NBATCH; ++bb) {
                float s_rec = 0.0f, s_dat = 0.0f;
                #pragma unroll
                for (int c = 0; c < CHUNKS; ++c) {
                    s_rec += g_partial[(0 * NBATCH + bb) * CHUNKS + c];
                    s_dat += g_partial[(1 * NBATCH + bb) * CHUNKS + c];
                }
                total += fmaxf(s_rec * (1.0f / NPTS), s_dat * (1.0f / NPTS));
            }
            out[0] = total * (1.0f / NBATCH);
            g_arrive = 0;   // reset for next graph replay
        }
    }
}

extern "C" void kernel_launch(void* const* d_in, const int* in_sizes, int n_in,
                              void* d_out, int out_size) {
    const float* rec  = (const float*)d_in[0];   // (B, N, 3) fp32
    const float* data = (const float*)d_in[1];   // (B, M, 3) fp32
    float* out = (float*)d_out;

    const size_t smem_bytes = 4 * NPTS * sizeof(float);  // 128 KB
    cudaFuncSetAttribute(chamfer_main,
                         cudaFuncAttributeMaxDynamicSharedMemorySize,
                         (int)smem_bytes);

    dim3 grid(CHUNKS, NBATCH, 2);
    chamfer_main<<<grid, THREADS, smem_bytes>>>(rec, data, out);
}

// round 3
// speedup vs baseline: 1.3922x; 1.0435x over previous
#include <cuda_runtime.h>

#define NBATCH   4
#define NPTS     8192
#define THREADS  256
#define QPT      4                       // queries per thread
#define QBLK     (THREADS * QPT)         // 1024 queries per block
#define CHUNKS   (NPTS / QBLK)           // 8 query chunks
#define QUARTERS 4                       // db split
#define DBQ      (NPTS / QUARTERS)       // 2048 db points per block

// Per-query clamped quarter-min: [dir*NBATCH+b][quarter][query].
// Every slot overwritten each launch -> deterministic, no init needed.
__device__ float g_min[2 * NBATCH][QUARTERS][NPTS];

typedef unsigned long long ull;

__device__ __forceinline__ ull ffma2(ull a, ull b, ull c) {
    ull d;
    asm("fma.rn.f32x2 %0, %1, %2, %3;" : "=l"(d) : "l"(a), "l"(b), "l"(c));
    return d;
}
__device__ __forceinline__ ull pack2(float lo, float hi) {
    ull d;
    asm("mov.b64 %0, {%1, %2};" : "=l"(d) : "f"(lo), "f"(hi));
    return d;
}
__device__ __forceinline__ float2 unpack2(ull v) {
    float2 r;
    asm("mov.b64 {%0, %1}, %2;" : "=f"(r.x), "=f"(r.y) : "l"(v));
    return r;
}

__global__ __launch_bounds__(THREADS, 2)
void chamfer_main(const float* __restrict__ rec,
                  const float* __restrict__ data) {
    __shared__ float s0[DBQ];
    __shared__ float s1[DBQ];
    __shared__ float s2[DBQ];
    __shared__ float sn[DBQ];

    const int tid     = threadIdx.x;
    const int quarter = blockIdx.x & (QUARTERS - 1);
    const int chunk   = blockIdx.x >> 2;          // 0..CHUNKS-1
    const int b       = blockIdx.y;
    const int dir     = blockIdx.z;

    // dir 0: queries = rec, database = data   (rec_dist)
    // dir 1: queries = data, database = rec   (data_dist)
    const float* __restrict__ qry = dir ? data : rec;
    const float* __restrict__ db  = dir ? rec  : data;

    // ---- Load this db quarter into SMEM (SoA + precomputed norms) ----
    const float* dbb = db + ((size_t)b * NPTS + quarter * DBQ) * 3;
    #pragma unroll
    for (int k = 0; k < DBQ / THREADS; ++k) {
        int i = tid + k * THREADS;
        float x = dbb[3 * i + 0];
        float y = dbb[3 * i + 1];
        float z = dbb[3 * i + 2];
        s0[i] = x;
        s1[i] = y;
        s2[i] = z;
        sn[i] = fmaf(x, x, fmaf(y, y, z * z));
    }

    // ---- Per-thread query points (4, coalesced across warp) ----
    float q2[QPT];
    ull A0[QPT], A1[QPT], A2[QPT];
    #pragma unroll
    for (int q = 0; q < QPT; ++q) {
        int qi = chunk * QBLK + q * THREADS + tid;
        const float* qp = qry + ((size_t)b * NPTS + qi) * 3;
        float qx = qp[0], qy = qp[1], qz = qp[2];
        q2[q] = fmaf(qx, qx, fmaf(qy, qy, qz * qz));
        A0[q] = pack2(-2.0f * qx, -2.0f * qx);
        A1[q] = pack2(-2.0f * qy, -2.0f * qy);
        A2[q] = pack2(-2.0f * qz, -2.0f * qz);
    }

    __syncthreads();

    // ---- Main loop: min_j ( ||y_j||^2 - 2 x . y_j )
    //      4 db points per step (broadcast LDS.128), 4 queries per thread ----
    float m0[QPT], m1[QPT], m2[QPT], m3[QPT];
    #pragma unroll
    for (int q = 0; q < QPT; ++q) { m0[q] = m1[q] = m2[q] = m3[q] = 1e30f; }

    #pragma unroll 2
    for (int j = 0; j < DBQ; j += 4) {
        ulonglong2 p0 = *reinterpret_cast<const ulonglong2*>(s0 + j);
        ulonglong2 p1 = *reinterpret_cast<const ulonglong2*>(s1 + j);
        ulonglong2 p2 = *reinterpret_cast<const ulonglong2*>(s2 + j);
        ulonglong2 pn = *reinterpret_cast<const ulonglong2*>(sn + j);

        #pragma unroll
        for (int q = 0; q < QPT; ++q) {
            ull accA = ffma2(A2[q], p2.x, pn.x);
            accA     = ffma2(A1[q], p1.x, accA);
            accA     = ffma2(A0[q], p0.x, accA);

            ull accB = ffma2(A2[q], p2.y, pn.y);
            accB     = ffma2(A1[q], p1.y, accB);
            accB     = ffma2(A0[q], p0.y, accB);

            float2 fa = unpack2(accA);
            float2 fb = unpack2(accB);
            m0[q] = fminf(m0[q], fa.x);
            m1[q] = fminf(m1[q], fa.y);
            m2[q] = fminf(m2[q], fb.x);
            m3[q] = fminf(m3[q], fb.y);
        }
    }

    // ---- Per-query clamped quarter-min -> global slot (coalesced stores) ----
    const int base = chunk * QBLK + tid;
    #pragma unroll
    for (int q = 0; q < QPT; ++q) {
        float mmin = fminf(fminf(m0[q], m1[q]), fminf(m2[q], m3[q]));
        float dist = fmaxf(q2[q] + mmin, 0.0f);   // clamp commutes with min
        g_min[dir * NBATCH + b][quarter][base + q * THREADS] = dist;
    }
}

#define RTHREADS 1024

__global__ __launch_bounds__(RTHREADS)
void chamfer_reduce(float* __restrict__ out) {
    __shared__ float red[RTHREADS];
    __shared__ float groupsum[2 * NBATCH];
    const int tid = threadIdx.x;

    #pragma unroll
    for (int g = 0; g < 2 * NBATCH; ++g) {
        float s = 0.0f;
        for (int q = tid; q < NPTS; q += RTHREADS) {
            float m = fminf(fminf(g_min[g][0][q], g_min[g][1][q]),
                            fminf(g_min[g][2][q], g_min[g][3][q]));
            s += m;
        }
        red[tid] = s;
        __syncthreads();
        #pragma unroll
        for (int st = RTHREADS / 2; st > 0; st >>= 1) {
            if (tid < st) red[tid] += red[tid + st];
            __syncthreads();
        }
        if (tid == 0) groupsum[g] = red[0];
        __syncthreads();
    }

    if (tid == 0) {
        float total = 0.0f;
        #pragma unroll
        for (int bb = 0; bb < NBATCH; ++bb) {
            float mean_rec = groupsum[0 * NBATCH + bb] * (1.0f / NPTS);
            float mean_dat = groupsum[1 * NBATCH + bb] * (1.0f / NPTS);
            total += fmaxf(mean_rec, mean_dat);
        }
        out[0] = total * (1.0f / NBATCH);
    }
}

extern "C" void kernel_launch(void* const* d_in, const int* in_sizes, int n_in,
                              void* d_out, int out_size) {
    const float* rec  = (const float*)d_in[0];   // (B, N, 3) fp32
    const float* data = (const float*)d_in[1];   // (B, M, 3) fp32
    float* out = (float*)d_out;

    dim3 grid(CHUNKS * QUARTERS, NBATCH, 2);     // 32 x 4 x 2 = 256 blocks
    chamfer_main<<<grid, THREADS>>>(rec, data);
    chamfer_reduce<<<1, RTHREADS>>>(out);
}

// round 4
// speedup vs baseline: 1.5213x; 1.0927x over previous
#include <cuda_runtime.h>

#define NBATCH   4
#define NPTS     8192
#define THREADS  256
#define QPT      4                       // queries per thread
#define QBLK     (THREADS * QPT)         // 1024 queries per block
#define CHUNKS   (NPTS / QBLK)           // 8 query chunks
#define EIGHTHS  8                       // db split
#define DBE      (NPTS / EIGHTHS)        // 1024 db points per block
#define GROUPS   (2 * NBATCH)            // 8 (dir,b) groups
#define BLOCKS_PER_GROUP (CHUNKS * EIGHTHS)   // 64

// Per-query clamped eighth-min: [group][eighth][query]. Every slot is
// overwritten each launch -> deterministic, no init needed. (2 MB)
__device__ float        g_min[GROUPS][EIGHTHS][NPTS];
__device__ float        g_groupsum[GROUPS];
__device__ unsigned int g_cnt[GROUPS];   // zero-init; reset by final finisher
__device__ unsigned int g_cnt2;          // zero-init; reset by final finisher

typedef unsigned long long ull;

__device__ __forceinline__ ull ffma2(ull a, ull b, ull c) {
    ull d;
    asm("fma.rn.f32x2 %0, %1, %2, %3;" : "=l"(d) : "l"(a), "l"(b), "l"(c));
    return d;
}
__device__ __forceinline__ ull pack2(float lo, float hi) {
    ull d;
    asm("mov.b64 %0, {%1, %2};" : "=l"(d) : "f"(lo), "f"(hi));
    return d;
}
__device__ __forceinline__ float2 unpack2(ull v) {
    float2 r;
    asm("mov.b64 {%0, %1}, %2;" : "=f"(r.x), "=f"(r.y) : "l"(v));
    return r;
}

__global__ __launch_bounds__(THREADS, 3)
void chamfer_main(const float* __restrict__ rec,
                  const float* __restrict__ data,
                  float* __restrict__ out) {
    __shared__ float s0[DBE];
    __shared__ float s1[DBE];
    __shared__ float s2[DBE];
    __shared__ float sn[DBE];
    __shared__ float red[THREADS];
    __shared__ int   s_flag;

    const int tid    = threadIdx.x;
    const int eighth = blockIdx.x & (EIGHTHS - 1);
    const int chunk  = blockIdx.x >> 3;           // 0..CHUNKS-1
    const int b      = blockIdx.y;
    const int dir    = blockIdx.z;
    const int group  = dir * NBATCH + b;

    // dir 0: queries = rec, database = data   (rec_dist)
    // dir 1: queries = data, database = rec   (data_dist)
    const float* __restrict__ qry = dir ? data : rec;
    const float* __restrict__ db  = dir ? rec  : data;

    // ---- Load this db eighth into SMEM (SoA + precomputed norms) ----
    const float* dbb = db + ((size_t)b * NPTS + eighth * DBE) * 3;
    #pragma unroll
    for (int k = 0; k < DBE / THREADS; ++k) {
        int i = tid + k * THREADS;
        float x = dbb[3 * i + 0];
        float y = dbb[3 * i + 1];
        float z = dbb[3 * i + 2];
        s0[i] = x;
        s1[i] = y;
        s2[i] = z;
        sn[i] = fmaf(x, x, fmaf(y, y, z * z));
    }

    // ---- Per-thread query points (4, coalesced across warp) ----
    float q2[QPT];
    ull A0[QPT], A1[QPT], A2[QPT];
    #pragma unroll
    for (int q = 0; q < QPT; ++q) {
        int qi = chunk * QBLK + q * THREADS + tid;
        const float* qp = qry + ((size_t)b * NPTS + qi) * 3;
        float qx = qp[0], qy = qp[1], qz = qp[2];
        q2[q] = fmaf(qx, qx, fmaf(qy, qy, qz * qz));
        A0[q] = pack2(-2.0f * qx, -2.0f * qx);
        A1[q] = pack2(-2.0f * qy, -2.0f * qy);
        A2[q] = pack2(-2.0f * qz, -2.0f * qz);
    }

    __syncthreads();

    // ---- Main loop: min_j ( ||y_j||^2 - 2 x . y_j )
    //      4 db points per step (broadcast LDS.128), 4 queries per thread ----
    float m0[QPT], m1[QPT], m2[QPT], m3[QPT];
    #pragma unroll
    for (int q = 0; q < QPT; ++q) { m0[q] = m1[q] = m2[q] = m3[q] = 1e30f; }

    for (int j = 0; j < DBE; j += 4) {
        ulonglong2 p0 = *reinterpret_cast<const ulonglong2*>(s0 + j);
        ulonglong2 p1 = *reinterpret_cast<const ulonglong2*>(s1 + j);
        ulonglong2 p2 = *reinterpret_cast<const ulonglong2*>(s2 + j);
        ulonglong2 pn = *reinterpret_cast<const ulonglong2*>(sn + j);

        #pragma unroll
        for (int q = 0; q < QPT; ++q) {
            ull accA = ffma2(A2[q], p2.x, pn.x);
            accA     = ffma2(A1[q], p1.x, accA);
            accA     = ffma2(A0[q], p0.x, accA);

            ull accB = ffma2(A2[q], p2.y, pn.y);
            accB     = ffma2(A1[q], p1.y, accB);
            accB     = ffma2(A0[q], p0.y, accB);

            float2 fa = unpack2(accA);
            float2 fb = unpack2(accB);
            m0[q] = fminf(m0[q], fa.x);
            m1[q] = fminf(m1[q], fa.y);
            m2[q] = fminf(m2[q], fb.x);
            m3[q] = fminf(m3[q], fb.y);
        }
    }

    // ---- Per-query clamped eighth-min -> global slot (coalesced stores) ----
    const int base = chunk * QBLK + tid;
    #pragma unroll
    for (int q = 0; q < QPT; ++q) {
        float mmin = fminf(fminf(m0[q], m1[q]), fminf(m2[q], m3[q]));
        float dist = fmaxf(q2[q] + mmin, 0.0f);   // clamp commutes with min
        g_min[group][eighth][base + q * THREADS] = dist;
    }

    // ---- Fused reduce: last block of each group reduces that group ----
    if (tid == 0) {
        __threadfence();
        unsigned int t = atomicAdd(&g_cnt[group], 1u);
        s_flag = (t == BLOCKS_PER_GROUP - 1) ? 1 : 0;
    }
    __syncthreads();

    if (s_flag) {
        __threadfence();   // acquire: other blocks' g_min writes are visible
        float s = 0.0f;
        for (int q = tid * 4; q < NPTS; q += THREADS * 4) {
            float4 m = *reinterpret_cast<const float4*>(&g_min[group][0][q]);
            #pragma unroll
            for (int e = 1; e < EIGHTHS; ++e) {
                float4 v = *reinterpret_cast<const float4*>(&g_min[group][e][q]);
                m.x = fminf(m.x, v.x);
                m.y = fminf(m.y, v.y);
                m.z = fminf(m.z, v.z);
                m.w = fminf(m.w, v.w);
            }
            s += (m.x + m.y) + (m.z + m.w);
        }
        red[tid] = s;
        __syncthreads();
        #pragma unroll
        for (int st = THREADS / 2; st > 0; st >>= 1) {
            if (tid < st) red[tid] += red[tid + st];
            __syncthreads();
        }
        if (tid == 0) {
            g_groupsum[group] = red[0];
            __threadfence();
            unsigned int t2 = atomicAdd(&g_cnt2, 1u);
            if (t2 == GROUPS - 1) {
                __threadfence();
                float total = 0.0f;
                #pragma unroll
                for (int bb = 0; bb < NBATCH; ++bb) {
                    float mean_rec = g_groupsum[0 * NBATCH + bb] * (1.0f / NPTS);
                    float mean_dat = g_groupsum[1 * NBATCH + bb] * (1.0f / NPTS);
                    total += fmaxf(mean_rec, mean_dat);
                }
                out[0] = total * (1.0f / NBATCH);
                // reset counters for next graph replay
                #pragma unroll
                for (int gg = 0; gg < GROUPS; ++gg) g_cnt[gg] = 0u;
                g_cnt2 = 0u;
            }
        }
    }
}

extern "C" void kernel_launch(void* const* d_in, const int* in_sizes, int n_in,
                              void* d_out, int out_size) {
    const float* rec  = (const float*)d_in[0];   // (B, N, 3) fp32
    const float* data = (const float*)d_in[1];   // (B, M, 3) fp32
    float* out = (float*)d_out;

    dim3 grid(CHUNKS * EIGHTHS, NBATCH, 2);      // 64 x 4 x 2 = 512 blocks
    chamfer_main<<<grid, THREADS>>>(rec, data, out);
}